// round 6
// baseline (speedup 1.0000x reference)
#include <cuda_runtime.h>

#define NN 100000
#define DD 128
#define EPS 1e-5f

// ---------------- device scratch (no allocations allowed) ----------------
__device__ float g_h[(size_t)NN * DD];     // hs = (x@W)*dinv[row]; later h2; later h3
__device__ float g_acc[(size_t)NN * DD];   // scatter accumulator -> t; later h2n
__device__ float g_u[(size_t)NN * 256];    // FFN hidden
__device__ float g_deg[NN];
__device__ float g_dinv[NN];
__device__ float g_sum[3 * DD];
__device__ float g_sq[3 * DD];
__device__ float g_mean[3 * DD];
__device__ float g_rstd[3 * DD];

// ---------------- init ----------------
__global__ void init_kernel() {
    int i = blockIdx.x * blockDim.x + threadIdx.x;
    if (i < NN) g_deg[i] = 1.0f;           // self loop
    if (i < 3 * DD) { g_sum[i] = 0.f; g_sq[i] = 0.f; }
}

__global__ void degree_kernel(const int* __restrict__ ei, int E) {
    int e = blockIdx.x * blockDim.x + threadIdx.x;
    if (e < E) atomicAdd(&g_deg[ei[E + e]], 1.0f);
}

__global__ void dinv_kernel() {
    int i = blockIdx.x * blockDim.x + threadIdx.x;
    if (i < NN) g_dinv[i] = rsqrtf(g_deg[i]);
}

// ---------------- GEMM: 128x128 tile, 8x8 microtile, BK=32 ----------------
// MODE 0: C = (x @ W) * dinv[row] -> g_h AND g_acc   (K=128, NLD=128)
// MODE 1: g_u = relu(g_acc @ W1 + b1)                (K=128, NLD=256)
// MODE 2: g_h = g_u @ W2 + b2 + g_acc                (K=256, NLD=128)
template<int MODE, int K, int NLD>
__global__ __launch_bounds__(256) void gemm_kernel(const float* __restrict__ Ax,
                                                   const float* __restrict__ B,
                                                   const float* __restrict__ bias)
{
    __shared__ float As[32][DD];   // [k][row]
    __shared__ float Bs[32][DD];   // [k][col]
    const float* A = (MODE == 0) ? Ax : (MODE == 1 ? (const float*)g_acc : (const float*)g_u);

    int tid  = threadIdx.x;
    int row0 = blockIdx.x * 128;
    int col0 = blockIdx.y * 128;
    int tx = tid & 15, ty = tid >> 4;
    int trow = ty * 8, tcol = tx * 8;

    float acc[8][8];
#pragma unroll
    for (int i = 0; i < 8; i++)
#pragma unroll
        for (int j = 0; j < 8; j++) acc[i][j] = 0.f;

    int la_r = tid >> 3;          // 0..31, +i*32
    int la_k = (tid & 7) * 4;     // k float4 offset
    int lb_k = tid >> 5;          // 0..7, +i*8
    int lb_c = (tid & 31) * 4;    // col float4 offset

    for (int kt = 0; kt < K; kt += 32) {
#pragma unroll
        for (int i = 0; i < 4; i++) {
            int r = la_r + i * 32;
            int m = row0 + r;
            float4 v = make_float4(0.f, 0.f, 0.f, 0.f);
            if (m < NN) v = *(const float4*)(A + (size_t)m * K + kt + la_k);
            As[la_k + 0][r] = v.x;
            As[la_k + 1][r] = v.y;
            As[la_k + 2][r] = v.z;
            As[la_k + 3][r] = v.w;
        }
#pragma unroll
        for (int i = 0; i < 4; i++) {
            int kr = lb_k + i * 8;
            float4 v = *(const float4*)(B + (size_t)(kt + kr) * NLD + col0 + lb_c);
            *(float4*)&Bs[kr][lb_c] = v;
        }
        __syncthreads();
#pragma unroll 8
        for (int kk = 0; kk < 32; kk++) {
            float a[8], bb[8];
            *(float4*)&a[0]  = *(const float4*)&As[kk][trow];
            *(float4*)&a[4]  = *(const float4*)&As[kk][trow + 4];
            *(float4*)&bb[0] = *(const float4*)&Bs[kk][tcol];
            *(float4*)&bb[4] = *(const float4*)&Bs[kk][tcol + 4];
#pragma unroll
            for (int i = 0; i < 8; i++)
#pragma unroll
                for (int j = 0; j < 8; j++)
                    acc[i][j] += a[i] * bb[j];
        }
        __syncthreads();
    }

    // epilogue
    float bj[8];
    if (MODE != 0) {
#pragma unroll
        for (int j = 0; j < 8; j++) bj[j] = bias[col0 + tcol + j];
    }
#pragma unroll
    for (int i = 0; i < 8; i++) {
        int m = row0 + trow + i;
        if (m >= NN) continue;
        if (MODE == 0) {
            float dv = g_dinv[m];
            float4 v0, v1;
            v0.x = acc[i][0] * dv; v0.y = acc[i][1] * dv; v0.z = acc[i][2] * dv; v0.w = acc[i][3] * dv;
            v1.x = acc[i][4] * dv; v1.y = acc[i][5] * dv; v1.z = acc[i][6] * dv; v1.w = acc[i][7] * dv;
            size_t off = (size_t)m * DD + tcol;
            *(float4*)&g_h[off]     = v0; *(float4*)&g_h[off + 4]   = v1;
            *(float4*)&g_acc[off]   = v0; *(float4*)&g_acc[off + 4] = v1;   // self-loop init
        } else if (MODE == 1) {
            size_t off = (size_t)m * 256 + col0 + tcol;
            float4 v0, v1;
            v0.x = fmaxf(acc[i][0] + bj[0], 0.f); v0.y = fmaxf(acc[i][1] + bj[1], 0.f);
            v0.z = fmaxf(acc[i][2] + bj[2], 0.f); v0.w = fmaxf(acc[i][3] + bj[3], 0.f);
            v1.x = fmaxf(acc[i][4] + bj[4], 0.f); v1.y = fmaxf(acc[i][5] + bj[5], 0.f);
            v1.z = fmaxf(acc[i][6] + bj[6], 0.f); v1.w = fmaxf(acc[i][7] + bj[7], 0.f);
            *(float4*)&g_u[off] = v0; *(float4*)&g_u[off + 4] = v1;
        } else {
            size_t off = (size_t)m * DD + tcol;
            float4 r0 = *(const float4*)&g_acc[off];
            float4 r1 = *(const float4*)&g_acc[off + 4];
            float4 v0, v1;
            v0.x = acc[i][0] + bj[0] + r0.x; v0.y = acc[i][1] + bj[1] + r0.y;
            v0.z = acc[i][2] + bj[2] + r0.z; v0.w = acc[i][3] + bj[3] + r0.w;
            v1.x = acc[i][4] + bj[4] + r1.x; v1.y = acc[i][5] + bj[5] + r1.y;
            v1.z = acc[i][6] + bj[6] + r1.z; v1.w = acc[i][7] + bj[7] + r1.w;
            *(float4*)&g_h[off] = v0; *(float4*)&g_h[off + 4] = v1;
        }
    }
}

// ---------------- edge scatter: g_acc[d] += g_h[s] (vector RED) ----------------
__global__ __launch_bounds__(256) void scatter_kernel(const int* __restrict__ ei, int E) {
    __shared__ int ss[256], sd[256];
    int base = blockIdx.x * 256;
    int t = threadIdx.x;
    int e = base + t;
    if (e < E) { ss[t] = ei[e]; sd[t] = ei[E + e]; }
    __syncthreads();
    int lane = t & 31, warp = t >> 5;
    int nloc = min(256, E - base);
    for (int j = warp; j < nloc; j += 8) {
        int s = ss[j], d = sd[j];
        const float4 v = *(const float4*)(g_h + (size_t)s * DD + lane * 4);
        float4* dst = (float4*)(g_acc + (size_t)d * DD + lane * 4);
        asm volatile("red.global.add.v4.f32 [%0], {%1, %2, %3, %4};"
                     :: "l"(dst), "f"(v.x), "f"(v.y), "f"(v.z), "f"(v.w) : "memory");
    }
}

// ---------------- stats helper (block reduce + global atomic) ----------------
__device__ __forceinline__ void stats_reduce(int set, int lane,
                                             float s0, float s1, float s2, float s3,
                                             float q0, float q1, float q2, float q3) {
    __shared__ float ss[DD], sq[DD];
    if (threadIdx.x < DD) { ss[threadIdx.x] = 0.f; sq[threadIdx.x] = 0.f; }
    __syncthreads();
    int c = lane * 4;
    atomicAdd(&ss[c + 0], s0); atomicAdd(&ss[c + 1], s1);
    atomicAdd(&ss[c + 2], s2); atomicAdd(&ss[c + 3], s3);
    atomicAdd(&sq[c + 0], q0); atomicAdd(&sq[c + 1], q1);
    atomicAdd(&sq[c + 2], q2); atomicAdd(&sq[c + 3], q3);
    __syncthreads();
    if (threadIdx.x < DD) {
        atomicAdd(&g_sum[set * DD + threadIdx.x], ss[threadIdx.x]);
        atomicAdd(&g_sq[set * DD + threadIdx.x], sq[threadIdx.x]);
    }
}

// ---------------- t = acc*dinv + b (in place), stats set 0 ----------------
__global__ __launch_bounds__(256) void finalize_t_kernel(const float* __restrict__ b) {
    int gt = blockIdx.x * blockDim.x + threadIdx.x;
    int gw = gt >> 5, lane = threadIdx.x & 31;
    int nw = (gridDim.x * blockDim.x) >> 5;
    float4 bb = *(const float4*)(b + lane * 4);
    float s0 = 0, s1 = 0, s2 = 0, s3 = 0, q0 = 0, q1 = 0, q2 = 0, q3 = 0;
    for (int r = gw; r < NN; r += nw) {
        float dv = g_dinv[r];
        size_t off = (size_t)r * DD + lane * 4;
        float4 v = *(float4*)&g_acc[off];
        v.x = v.x * dv + bb.x; v.y = v.y * dv + bb.y;
        v.z = v.z * dv + bb.z; v.w = v.w * dv + bb.w;
        *(float4*)&g_acc[off] = v;
        s0 += v.x; s1 += v.y; s2 += v.z; s3 += v.w;
        q0 += v.x * v.x; q1 += v.y * v.y; q2 += v.z * v.z; q3 += v.w * v.w;
    }
    stats_reduce(0, lane, s0, s1, s2, s3, q0, q1, q2, q3);
}

__global__ void bn_reduce_kernel(int set) {
    int c = threadIdx.x;
    float m = g_sum[set * DD + c] * (1.0f / NN);
    float v = g_sq[set * DD + c] * (1.0f / NN) - m * m;
    g_mean[set * DD + c] = m;
    g_rstd[set * DD + c] = rsqrtf(v + EPS);
}

// ---------------- h2 = x + relu(bn1(t)) -> g_h, stats set 1 ----------------
__global__ __launch_bounds__(256) void passB_kernel(const float* __restrict__ x,
                                                    const float* __restrict__ gamma1,
                                                    const float* __restrict__ beta1) {
    int gt = blockIdx.x * blockDim.x + threadIdx.x;
    int gw = gt >> 5, lane = threadIdx.x & 31;
    int nw = (gridDim.x * blockDim.x) >> 5;
    int c = lane * 4;
    float4 g  = *(const float4*)(gamma1 + c);
    float4 be = *(const float4*)(beta1 + c);
    float4 mn = *(const float4*)&g_mean[0 * DD + c];
    float4 rs = *(const float4*)&g_rstd[0 * DD + c];
    float sc0 = g.x * rs.x, sh0 = be.x - sc0 * mn.x;
    float sc1 = g.y * rs.y, sh1 = be.y - sc1 * mn.y;
    float sc2 = g.z * rs.z, sh2 = be.z - sc2 * mn.z;
    float sc3 = g.w * rs.w, sh3 = be.w - sc3 * mn.w;
    float s0 = 0, s1 = 0, s2 = 0, s3 = 0, q0 = 0, q1 = 0, q2 = 0, q3 = 0;
    for (int r = gw; r < NN; r += nw) {
        size_t off = (size_t)r * DD + c;
        float4 t  = *(const float4*)&g_acc[off];
        float4 xv = *(const float4*)(x + off);
        float4 v;
        v.x = xv.x + fmaxf(sc0 * t.x + sh0, 0.f);
        v.y = xv.y + fmaxf(sc1 * t.y + sh1, 0.f);
        v.z = xv.z + fmaxf(sc2 * t.z + sh2, 0.f);
        v.w = xv.w + fmaxf(sc3 * t.w + sh3, 0.f);
        *(float4*)&g_h[off] = v;
        s0 += v.x; s1 += v.y; s2 += v.z; s3 += v.w;
        q0 += v.x * v.x; q1 += v.y * v.y; q2 += v.z * v.z; q3 += v.w * v.w;
    }
    stats_reduce(1, lane, s0, s1, s2, s3, q0, q1, q2, q3);
}

// ---------------- h2n = bn2(h2) -> g_acc ----------------
__global__ __launch_bounds__(256) void passC_kernel(const float* __restrict__ gamma2,
                                                    const float* __restrict__ beta2) {
    int total = NN * (DD / 4);
    for (int f = blockIdx.x * blockDim.x + threadIdx.x; f < total; f += gridDim.x * blockDim.x) {
        int c = (f & 31) * 4;
        float4 g  = *(const float4*)(gamma2 + c);
        float4 be = *(const float4*)(beta2 + c);
        float4 mn = *(const float4*)&g_mean[1 * DD + c];
        float4 rs = *(const float4*)&g_rstd[1 * DD + c];
        float4 h = ((const float4*)g_h)[f];
        float4 v;
        v.x = g.x * rs.x * (h.x - mn.x) + be.x;
        v.y = g.y * rs.y * (h.y - mn.y) + be.y;
        v.z = g.z * rs.z * (h.z - mn.z) + be.z;
        v.w = g.w * rs.w * (h.w - mn.w) + be.w;
        ((float4*)g_acc)[f] = v;
    }
}

// ---------------- stats of h3 (g_h) -> set 2 ----------------
__global__ __launch_bounds__(256) void stats3_kernel() {
    int gt = blockIdx.x * blockDim.x + threadIdx.x;
    int gw = gt >> 5, lane = threadIdx.x & 31;
    int nw = (gridDim.x * blockDim.x) >> 5;
    float s0 = 0, s1 = 0, s2 = 0, s3 = 0, q0 = 0, q1 = 0, q2 = 0, q3 = 0;
    for (int r = gw; r < NN; r += nw) {
        size_t off = (size_t)r * DD + lane * 4;
        float4 v = *(const float4*)&g_h[off];
        s0 += v.x; s1 += v.y; s2 += v.z; s3 += v.w;
        q0 += v.x * v.x; q1 += v.y * v.y; q2 += v.z * v.z; q3 += v.w * v.w;
    }
    stats_reduce(2, lane, s0, s1, s2, s3, q0, q1, q2, q3);
}

// ---------------- out = bn3(h3) ----------------
__global__ __launch_bounds__(256) void final_kernel(float* __restrict__ out,
                                                    const float* __restrict__ gamma3,
                                                    const float* __restrict__ beta3) {
    int total = NN * (DD / 4);
    for (int f = blockIdx.x * blockDim.x + threadIdx.x; f < total; f += gridDim.x * blockDim.x) {
        int c = (f & 31) * 4;
        float4 g  = *(const float4*)(gamma3 + c);
        float4 be = *(const float4*)(beta3 + c);
        float4 mn = *(const float4*)&g_mean[2 * DD + c];
        float4 rs = *(const float4*)&g_rstd[2 * DD + c];
        float4 h = ((const float4*)g_h)[f];
        float4 v;
        v.x = g.x * rs.x * (h.x - mn.x) + be.x;
        v.y = g.y * rs.y * (h.y - mn.y) + be.y;
        v.z = g.z * rs.z * (h.z - mn.z) + be.z;
        v.w = g.w * rs.w * (h.w - mn.w) + be.w;
        ((float4*)out)[f] = v;
    }
}

// ---------------- host ----------------
extern "C" void kernel_launch(void* const* d_in, const int* in_sizes, int n_in,
                              void* d_out, int out_size) {
    const float* x      = (const float*)d_in[0];
    const int*   ei     = (const int*)  d_in[1];
    const float* W      = (const float*)d_in[2];
    const float* b      = (const float*)d_in[3];
    const float* gamma1 = (const float*)d_in[4];
    const float* beta1  = (const float*)d_in[5];
    const float* gamma2 = (const float*)d_in[6];
    const float* beta2  = (const float*)d_in[7];
    const float* gamma3 = (const float*)d_in[8];
    const float* beta3  = (const float*)d_in[9];
    const float* W1     = (const float*)d_in[10];
    const float* b1     = (const float*)d_in[11];
    const float* W2     = (const float*)d_in[12];
    const float* b2     = (const float*)d_in[13];
    float* out = (float*)d_out;
    int E = in_sizes[1] / 2;

    init_kernel<<<(NN + 255) / 256, 256>>>();
    degree_kernel<<<(E + 255) / 256, 256>>>(ei, E);
    dinv_kernel<<<(NN + 255) / 256, 256>>>();

    gemm_kernel<0, 128, 128><<<dim3((NN + 127) / 128, 1), 256>>>(x, W, nullptr);
    scatter_kernel<<<(E + 255) / 256, 256>>>(ei, E);
    finalize_t_kernel<<<1024, 256>>>(b);
    bn_reduce_kernel<<<1, 128>>>(0);
    passB_kernel<<<1024, 256>>>(x, gamma1, beta1);
    bn_reduce_kernel<<<1, 128>>>(1);
    passC_kernel<<<2048, 256>>>(gamma2, beta2);
    gemm_kernel<1, 128, 256><<<dim3((NN + 127) / 128, 2), 256>>>(nullptr, W1, b1);
    gemm_kernel<2, 256, 128><<<dim3((NN + 127) / 128, 1), 256>>>(nullptr, W2, b2);
    stats3_kernel<<<1024, 256>>>();
    bn_reduce_kernel<<<1, 128>>>(2);
    final_kernel<<<2048, 256>>>(out, gamma3, beta3);
}

// round 7
// speedup vs baseline: 1.5524x; 1.5524x over previous
#include <cuda_runtime.h>
#include <cstdint>

#define NN 100000
#define DD 128
#define EPS 1e-5f
#define EMAX 3200000
#define NBLK_SCAN 98   // ceil(NN/1024)

// ---------------- device scratch (no allocations allowed) ----------------
__device__ float g_h[(size_t)NN * DD];     // hs = (x@W)*dinv[row]; later h3
__device__ float g_acc[(size_t)NN * DD];   // t; later h2n (residual for mode2)
__device__ float g_u[(size_t)NN * 256];    // FFN hidden
__device__ float g_dinv[NN];
__device__ int   g_cnt[NN];
__device__ int   g_off[NN];
__device__ int   g_cursor[NN];
__device__ int   g_bsum[NBLK_SCAN];
__device__ int   g_srcs[EMAX];
__device__ float g_sum[3 * DD];
__device__ float g_sq[3 * DD];
__device__ float g_mean[3 * DD];
__device__ float g_rstd[3 * DD];

// ---------------- small helpers ----------------
__device__ __forceinline__ float f2tf32(float x) {
    uint32_t u;
    asm("cvt.rna.tf32.f32 %0, %1;" : "=r"(u) : "f"(x));
    return __uint_as_float(u);
}

__device__ __forceinline__ void mma_tf32(float4& d, const uint4& a, const uint2& b) {
    asm volatile(
        "mma.sync.aligned.m16n8k8.row.col.f32.tf32.tf32.f32 "
        "{%0,%1,%2,%3}, {%4,%5,%6,%7}, {%8,%9}, {%0,%1,%2,%3};"
        : "+f"(d.x), "+f"(d.y), "+f"(d.z), "+f"(d.w)
        : "r"(a.x), "r"(a.y), "r"(a.z), "r"(a.w), "r"(b.x), "r"(b.y));
}

// ---------------- init / degree / CSR build ----------------
__global__ void init_kernel() {
    int i = blockIdx.x * blockDim.x + threadIdx.x;
    if (i < NN) g_cnt[i] = 0;
    if (i < 3 * DD) { g_sum[i] = 0.f; g_sq[i] = 0.f; }
}

__global__ void count_kernel(const int* __restrict__ ei, int E) {
    int e = blockIdx.x * blockDim.x + threadIdx.x;
    if (e < E) atomicAdd(&g_cnt[ei[E + e]], 1);
}

__global__ void scan1_kernel() {
    __shared__ int sh[256];
    int blk = blockIdx.x, tid = threadIdx.x;
    int i0 = blk * 1024 + tid * 4;
    int c0 = (i0 + 0 < NN) ? g_cnt[i0 + 0] : 0;
    int c1 = (i0 + 1 < NN) ? g_cnt[i0 + 1] : 0;
    int c2 = (i0 + 2 < NN) ? g_cnt[i0 + 2] : 0;
    int c3 = (i0 + 3 < NN) ? g_cnt[i0 + 3] : 0;
    int s = c0 + c1 + c2 + c3;
    sh[tid] = s;
    __syncthreads();
    for (int off = 1; off < 256; off <<= 1) {
        int v = (tid >= off) ? sh[tid - off] : 0;
        __syncthreads();
        sh[tid] += v;
        __syncthreads();
    }
    int excl = sh[tid] - s;
    if (tid == 255) g_bsum[blk] = sh[255];
    if (i0 + 0 < NN) g_off[i0 + 0] = excl;
    if (i0 + 1 < NN) g_off[i0 + 1] = excl + c0;
    if (i0 + 2 < NN) g_off[i0 + 2] = excl + c0 + c1;
    if (i0 + 3 < NN) g_off[i0 + 3] = excl + c0 + c1 + c2;
}

__global__ void scan2_kernel() {
    if (threadIdx.x == 0) {
        int run = 0;
        for (int i = 0; i < NBLK_SCAN; i++) { int t = g_bsum[i]; g_bsum[i] = run; run += t; }
    }
}

__global__ void scan3_kernel() {
    int i = blockIdx.x * blockDim.x + threadIdx.x;
    if (i < NN) {
        int v = g_off[i] + g_bsum[i >> 10];
        g_off[i] = v;
        g_cursor[i] = v;
        g_dinv[i] = rsqrtf(1.0f + (float)g_cnt[i]);   // self loop included
    }
}

__global__ void fill_kernel(const int* __restrict__ ei, int E) {
    int e = blockIdx.x * blockDim.x + threadIdx.x;
    if (e < E) {
        int d = ei[E + e];
        int p = atomicAdd(&g_cursor[d], 1);
        g_srcs[p] = ei[e];
    }
}

// ---------------- tf32 tensor-core GEMM ----------------
// Tile 128x128, BK=32, 256 threads = 8 warps (2x4), warp tile 64x32.
// SMEM holds fragment-major permuted tf32 tiles.
// MODE 0: C = (x @ W) * dinv[row] -> g_h              (K=128, NLD=128)
// MODE 1: g_u = relu(g_acc @ W1 + b1)                 (K=128, NLD=256)
// MODE 2: g_h = g_u @ W2 + b2 + g_acc                 (K=256, NLD=128)
template<int MODE, int K, int NLD>
__global__ __launch_bounds__(256) void gemm_tc(const float* __restrict__ Ax,
                                               const float* __restrict__ B,
                                               const float* __restrict__ bias)
{
    __shared__ __align__(16) float As[4096];  // [slice(4)][am(8)][lane(32)][reg(4)]
    __shared__ __align__(16) float Bs[4096];  // [slice(4)][bn(16)][lane(32)][reg(2)]
    const float* A = (MODE == 0) ? Ax : (MODE == 1 ? (const float*)g_acc : (const float*)g_u);

    int tid = threadIdx.x;
    int row0 = blockIdx.x * 128;
    int col0 = blockIdx.y * 128;
    int lane = tid & 31, wid = tid >> 5;
    int warp_m = wid & 1;        // 0..1 -> 64-row half
    int warp_n = wid >> 1;       // 0..3 -> 32-col quarter

    float4 c[4][4];
#pragma unroll
    for (int i = 0; i < 4; i++)
#pragma unroll
        for (int j = 0; j < 4; j++) c[i][j] = make_float4(0.f, 0.f, 0.f, 0.f);

    // A load mapping: row = (tid>>3)+i*32, k = (tid&7)*4 .. +3
    int la_r = tid >> 3;
    int la_k = (tid & 7) * 4;
    // B load mapping: k = (tid&7)+i*8, col = (tid>>3)*4 .. +3
    int lbk = tid & 7;
    int lbc = (tid >> 3) * 4;

    for (int kt = 0; kt < K; kt += 32) {
        // ---- A tile -> permuted smem ----
#pragma unroll
        for (int i = 0; i < 4; i++) {
            int r = la_r + i * 32;
            int m = row0 + r;
            float4 v = make_float4(0.f, 0.f, 0.f, 0.f);
            if (m < NN) v = *(const float4*)(A + (size_t)m * K + kt + la_k);
            int s  = la_k >> 3;
            int am = r >> 4, rr = r & 15;
            // slot(c) = (rr&7)*4 + c, reg = (rr>>3) + 2*((la_k>>2)&1)
            int base = ((s * 8 + am) * 32 + (rr & 7) * 4) * 4 + (rr >> 3) + ((la_k >> 2) & 1) * 2;
            As[base + 0]  = f2tf32(v.x);
            As[base + 4]  = f2tf32(v.y);
            As[base + 8]  = f2tf32(v.z);
            As[base + 12] = f2tf32(v.w);
        }
        // ---- B tile -> permuted smem ----
#pragma unroll
        for (int i = 0; i < 4; i++) {
            int k = lbk + i * 8;
            float4 v = *(const float4*)(B + (size_t)(kt + k) * NLD + col0 + lbc);
            int s  = k >> 3;            // == i
            int bn = lbc >> 3;
            int c7 = lbc & 7;
            // slot(cc) = (c7+cc)*4 + (k&3), reg = (k>>2)&1
            int base = ((s * 16 + bn) * 32 + c7 * 4 + (k & 3)) * 2 + ((k >> 2) & 1);
            Bs[base + 0]  = f2tf32(v.x);
            Bs[base + 8]  = f2tf32(v.y);
            Bs[base + 16] = f2tf32(v.z);
            Bs[base + 24] = f2tf32(v.w);
        }
        __syncthreads();
#pragma unroll
        for (int s = 0; s < 4; s++) {
            uint4 a[4];
            uint2 bf[4];
#pragma unroll
            for (int i = 0; i < 4; i++)
                a[i] = *(const uint4*)&As[((s * 8 + warp_m * 4 + i) * 32 + lane) * 4];
#pragma unroll
            for (int j = 0; j < 4; j++)
                bf[j] = *(const uint2*)&Bs[((s * 16 + warp_n * 4 + j) * 32 + lane) * 2];
#pragma unroll
            for (int i = 0; i < 4; i++)
#pragma unroll
                for (int j = 0; j < 4; j++)
                    mma_tf32(c[i][j], a[i], bf[j]);
        }
        __syncthreads();
    }

    // ---- epilogue ----
    int g = lane >> 2, tk = lane & 3;
#pragma unroll
    for (int i = 0; i < 4; i++) {
        int rx = row0 + warp_m * 64 + i * 16 + g;
        int rz = rx + 8;
        if (MODE == 0) {
            float dx = (rx < NN) ? g_dinv[rx] : 0.f;
            float dz = (rz < NN) ? g_dinv[rz] : 0.f;
#pragma unroll
            for (int j = 0; j < 4; j++) {
                int cc = col0 + warp_n * 32 + j * 8 + tk * 2;
                if (rx < NN) {
                    float2 v = make_float2(c[i][j].x * dx, c[i][j].y * dx);
                    *(float2*)&g_h[(size_t)rx * DD + cc] = v;
                }
                if (rz < NN) {
                    float2 v = make_float2(c[i][j].z * dz, c[i][j].w * dz);
                    *(float2*)&g_h[(size_t)rz * DD + cc] = v;
                }
            }
        } else if (MODE == 1) {
#pragma unroll
            for (int j = 0; j < 4; j++) {
                int cc = col0 + warp_n * 32 + j * 8 + tk * 2;
                float2 bv = *(const float2*)(bias + cc);
                if (rx < NN) {
                    float2 v = make_float2(fmaxf(c[i][j].x + bv.x, 0.f), fmaxf(c[i][j].y + bv.y, 0.f));
                    *(float2*)&g_u[(size_t)rx * 256 + cc] = v;
                }
                if (rz < NN) {
                    float2 v = make_float2(fmaxf(c[i][j].z + bv.x, 0.f), fmaxf(c[i][j].w + bv.y, 0.f));
                    *(float2*)&g_u[(size_t)rz * 256 + cc] = v;
                }
            }
        } else {
#pragma unroll
            for (int j = 0; j < 4; j++) {
                int cc = col0 + warp_n * 32 + j * 8 + tk * 2;
                float2 bv = *(const float2*)(bias + cc);
                if (rx < NN) {
                    float2 r = *(const float2*)&g_acc[(size_t)rx * DD + cc];
                    float2 v = make_float2(c[i][j].x + bv.x + r.x, c[i][j].y + bv.y + r.y);
                    *(float2*)&g_h[(size_t)rx * DD + cc] = v;
                }
                if (rz < NN) {
                    float2 r = *(const float2*)&g_acc[(size_t)rz * DD + cc];
                    float2 v = make_float2(c[i][j].z + bv.x + r.x, c[i][j].w + bv.y + r.y);
                    *(float2*)&g_h[(size_t)rz * DD + cc] = v;
                }
            }
        }
    }
}

// ---------------- stats helper (block reduce + global atomic) ----------------
__device__ __forceinline__ void stats_reduce(int set, int lane,
                                             float s0, float s1, float s2, float s3,
                                             float q0, float q1, float q2, float q3) {
    __shared__ float ss[DD], sq[DD];
    if (threadIdx.x < DD) { ss[threadIdx.x] = 0.f; sq[threadIdx.x] = 0.f; }
    __syncthreads();
    int c = lane * 4;
    atomicAdd(&ss[c + 0], s0); atomicAdd(&ss[c + 1], s1);
    atomicAdd(&ss[c + 2], s2); atomicAdd(&ss[c + 3], s3);
    atomicAdd(&sq[c + 0], q0); atomicAdd(&sq[c + 1], q1);
    atomicAdd(&sq[c + 2], q2); atomicAdd(&sq[c + 3], q3);
    __syncthreads();
    if (threadIdx.x < DD) {
        atomicAdd(&g_sum[set * DD + threadIdx.x], ss[threadIdx.x]);
        atomicAdd(&g_sq[set * DD + threadIdx.x], sq[threadIdx.x]);
    }
}

// ---------------- CSR gather: t[n] = (hs[n] + sum_s hs[s]) * dinv[n] + b ----------------
// One warp per node (grid-stride). Writes g_acc, accumulates BN stats set 0.
__global__ __launch_bounds__(256) void gather_kernel(const float* __restrict__ b) {
    int gw = (blockIdx.x * blockDim.x + threadIdx.x) >> 5;
    int lane = threadIdx.x & 31;
    int nw = (gridDim.x * blockDim.x) >> 5;
    float4 bb = *(const float4*)(b + lane * 4);
    float s0 = 0, s1 = 0, s2 = 0, s3 = 0, q0 = 0, q1 = 0, q2 = 0, q3 = 0;
    for (int n = gw; n < NN; n += nw) {
        int st = g_off[n];
        int en = g_cursor[n];             // off[n] + cnt[n]
        size_t base = (size_t)n * DD + lane * 4;
        float4 acc = *(const float4*)&g_h[base];   // self loop term
        for (int j = st; j < en; j++) {
            int s = g_srcs[j];
            float4 v = *(const float4*)&g_h[(size_t)s * DD + lane * 4];
            acc.x += v.x; acc.y += v.y; acc.z += v.z; acc.w += v.w;
        }
        float dv = g_dinv[n];
        float4 t;
        t.x = acc.x * dv + bb.x; t.y = acc.y * dv + bb.y;
        t.z = acc.z * dv + bb.z; t.w = acc.w * dv + bb.w;
        *(float4*)&g_acc[base] = t;
        s0 += t.x; s1 += t.y; s2 += t.z; s3 += t.w;
        q0 += t.x * t.x; q1 += t.y * t.y; q2 += t.z * t.z; q3 += t.w * t.w;
    }
    stats_reduce(0, lane, s0, s1, s2, s3, q0, q1, q2, q3);
}

__global__ void bn_reduce_kernel(int set) {
    int c = threadIdx.x;
    float m = g_sum[set * DD + c] * (1.0f / NN);
    float v = g_sq[set * DD + c] * (1.0f / NN) - m * m;
    g_mean[set * DD + c] = m;
    g_rstd[set * DD + c] = rsqrtf(v + EPS);
}

// ---------------- h2 = x + relu(bn1(t)) -> g_h, stats set 1 ----------------
__global__ __launch_bounds__(256) void passB_kernel(const float* __restrict__ x,
                                                    const float* __restrict__ gamma1,
                                                    const float* __restrict__ beta1) {
    int gt = blockIdx.x * blockDim.x + threadIdx.x;
    int gw = gt >> 5, lane = threadIdx.x & 31;
    int nw = (gridDim.x * blockDim.x) >> 5;
    int c = lane * 4;
    float4 g  = *(const float4*)(gamma1 + c);
    float4 be = *(const float4*)(beta1 + c);
    float4 mn = *(const float4*)&g_mean[0 * DD + c];
    float4 rs = *(const float4*)&g_rstd[0 * DD + c];
    float sc0 = g.x * rs.x, sh0 = be.x - sc0 * mn.x;
    float sc1 = g.y * rs.y, sh1 = be.y - sc1 * mn.y;
    float sc2 = g.z * rs.z, sh2 = be.z - sc2 * mn.z;
    float sc3 = g.w * rs.w, sh3 = be.w - sc3 * mn.w;
    float s0 = 0, s1 = 0, s2 = 0, s3 = 0, q0 = 0, q1 = 0, q2 = 0, q3 = 0;
    for (int r = gw; r < NN; r += nw) {
        size_t off = (size_t)r * DD + c;
        float4 t  = *(const float4*)&g_acc[off];
        float4 xv = *(const float4*)(x + off);
        float4 v;
        v.x = xv.x + fmaxf(sc0 * t.x + sh0, 0.f);
        v.y = xv.y + fmaxf(sc1 * t.y + sh1, 0.f);
        v.z = xv.z + fmaxf(sc2 * t.z + sh2, 0.f);
        v.w = xv.w + fmaxf(sc3 * t.w + sh3, 0.f);
        *(float4*)&g_h[off] = v;
        s0 += v.x; s1 += v.y; s2 += v.z; s3 += v.w;
        q0 += v.x * v.x; q1 += v.y * v.y; q2 += v.z * v.z; q3 += v.w * v.w;
    }
    stats_reduce(1, lane, s0, s1, s2, s3, q0, q1, q2, q3);
}

// ---------------- h2n = bn2(h2) -> g_acc ----------------
__global__ __launch_bounds__(256) void passC_kernel(const float* __restrict__ gamma2,
                                                    const float* __restrict__ beta2) {
    int total = NN * (DD / 4);
    for (int f = blockIdx.x * blockDim.x + threadIdx.x; f < total; f += gridDim.x * blockDim.x) {
        int c = (f & 31) * 4;
        float4 g  = *(const float4*)(gamma2 + c);
        float4 be = *(const float4*)(beta2 + c);
        float4 mn = *(const float4*)&g_mean[1 * DD + c];
        float4 rs = *(const float4*)&g_rstd[1 * DD + c];
        float4 h = ((const float4*)g_h)[f];
        float4 v;
        v.x = g.x * rs.x * (h.x - mn.x) + be.x;
        v.y = g.y * rs.y * (h.y - mn.y) + be.y;
        v.z = g.z * rs.z * (h.z - mn.z) + be.z;
        v.w = g.w * rs.w * (h.w - mn.w) + be.w;
        ((float4*)g_acc)[f] = v;
    }
}

// ---------------- stats of h3 (g_h) -> set 2 ----------------
__global__ __launch_bounds__(256) void stats3_kernel() {
    int gt = blockIdx.x * blockDim.x + threadIdx.x;
    int gw = gt >> 5, lane = threadIdx.x & 31;
    int nw = (gridDim.x * blockDim.x) >> 5;
    float s0 = 0, s1 = 0, s2 = 0, s3 = 0, q0 = 0, q1 = 0, q2 = 0, q3 = 0;
    for (int r = gw; r < NN; r += nw) {
        size_t off = (size_t)r * DD + lane * 4;
        float4 v = *(const float4*)&g_h[off];
        s0 += v.x; s1 += v.y; s2 += v.z; s3 += v.w;
        q0 += v.x * v.x; q1 += v.y * v.y; q2 += v.z * v.z; q3 += v.w * v.w;
    }
    stats_reduce(2, lane, s0, s1, s2, s3, q0, q1, q2, q3);
}

// ---------------- out = bn3(h3) ----------------
__global__ __launch_bounds__(256) void final_kernel(float* __restrict__ out,
                                                    const float* __restrict__ gamma3,
                                                    const float* __restrict__ beta3) {
    int total = NN * (DD / 4);
    for (int f = blockIdx.x * blockDim.x + threadIdx.x; f < total; f += gridDim.x * blockDim.x) {
        int c = (f & 31) * 4;
        float4 g  = *(const float4*)(gamma3 + c);
        float4 be = *(const float4*)(beta3 + c);
        float4 mn = *(const float4*)&g_mean[2 * DD + c];
        float4 rs = *(const float4*)&g_rstd[2 * DD + c];
        float4 h = ((const float4*)g_h)[f];
        float4 v;
        v.x = g.x * rs.x * (h.x - mn.x) + be.x;
        v.y = g.y * rs.y * (h.y - mn.y) + be.y;
        v.z = g.z * rs.z * (h.z - mn.z) + be.z;
        v.w = g.w * rs.w * (h.w - mn.w) + be.w;
        ((float4*)out)[f] = v;
    }
}

// ---------------- host ----------------
extern "C" void kernel_launch(void* const* d_in, const int* in_sizes, int n_in,
                              void* d_out, int out_size) {
    const float* x      = (const float*)d_in[0];
    const int*   ei     = (const int*)  d_in[1];
    const float* W      = (const float*)d_in[2];
    const float* b      = (const float*)d_in[3];
    const float* gamma1 = (const float*)d_in[4];
    const float* beta1  = (const float*)d_in[5];
    const float* gamma2 = (const float*)d_in[6];
    const float* beta2  = (const float*)d_in[7];
    const float* gamma3 = (const float*)d_in[8];
    const float* beta3  = (const float*)d_in[9];
    const float* W1     = (const float*)d_in[10];
    const float* b1     = (const float*)d_in[11];
    const float* W2     = (const float*)d_in[12];
    const float* b2     = (const float*)d_in[13];
    float* out = (float*)d_out;
    int E = in_sizes[1] / 2;

    init_kernel<<<(NN + 255) / 256, 256>>>();
    count_kernel<<<(E + 255) / 256, 256>>>(ei, E);
    scan1_kernel<<<NBLK_SCAN, 256>>>();
    scan2_kernel<<<1, 32>>>();
    scan3_kernel<<<(NN + 255) / 256, 256>>>();

    gemm_tc<0, 128, 128><<<dim3((NN + 127) / 128, 1), 256>>>(x, W, nullptr);
    fill_kernel<<<(E + 255) / 256, 256>>>(ei, E);
    gather_kernel<<<2048, 256>>>(b);
    bn_reduce_kernel<<<1, 128>>>(0);
    passB_kernel<<<1024, 256>>>(x, gamma1, beta1);
    bn_reduce_kernel<<<1, 128>>>(1);
    passC_kernel<<<2048, 256>>>(gamma2, beta2);
    gemm_tc<1, 128, 256><<<dim3((NN + 127) / 128, 2), 256>>>(nullptr, W1, b1);
    gemm_tc<2, 256, 128><<<dim3((NN + 127) / 128, 1), 256>>>(nullptr, W2, b2);
    stats3_kernel<<<1024, 256>>>();
    bn_reduce_kernel<<<1, 128>>>(2);
    final_kernel<<<2048, 256>>>(out, gamma3, beta3);
}